// round 3
// baseline (speedup 1.0000x reference)
#include <cuda_runtime.h>
#include <cstddef>

#define BATCH 512
#define TT    512
#define DD    128
#define DOUTN 32
#define CCLS  4

#define ALPHA_C 0.1f
#define GAMMA_C 0.9f
#define EPS_C   1e-5f
#define EPSH_C  1e-6f
#define LNEPS_C 1e-5f

__device__ __forceinline__ float warp_sum(float v) {
#pragma unroll
    for (int s = 16; s > 0; s >>= 1)
        v += __shfl_xor_sync(0xffffffffu, v, s, 32);
    return v;
}

__device__ __forceinline__ unsigned long long fma2(unsigned long long a,
                                                   unsigned long long b,
                                                   unsigned long long c) {
    unsigned long long d;
    asm("fma.rn.f32x2 %0, %1, %2, %3;" : "=l"(d) : "l"(a), "l"(b), "l"(c));
    return d;
}

__device__ __forceinline__ unsigned long long pack2(float lo, float hi) {
    unsigned long long r;
    asm("mov.b64 %0, {%1, %2};" : "=l"(r) : "f"(lo), "f"(hi));
    return r;
}

__device__ __forceinline__ void unpack2(unsigned long long v, float& lo, float& hi) {
    asm("mov.b64 {%0, %1}, %2;" : "=f"(lo), "=f"(hi) : "l"(v));
}

__global__ __launch_bounds__(128, 1)
void sync_head_kernel(const float* __restrict__ z_ticks,
                      const float* __restrict__ proj,
                      const float* __restrict__ ln_w,
                      const float* __restrict__ ln_b,
                      const float* __restrict__ cls_w,
                      const float* __restrict__ cls_b,
                      float* __restrict__ out_x,
                      float* __restrict__ out_logits) {
    __shared__ float sZ[4][DD];

    const int lane  = threadIdx.x & 31;
    const int w     = threadIdx.x >> 5;
    const int batch = blockIdx.x * 4 + w;

    // ---- hoist proj column `lane` into registers, packed for f32x2 FMA ----
    unsigned long long q[DD / 2];
#pragma unroll
    for (int i = 0; i < DD / 2; i++) {
        float a = proj[(2 * i) * DOUTN + lane];
        float b = proj[(2 * i + 1) * DOUTN + lane];
        q[i] = pack2(a, b);
    }

    // ---- fold LayerNorm affine + classifier into per-lane constants ----
    const float lw = ln_w[lane];
    const float lb = ln_b[lane];
    const float w0 = cls_w[0 * DOUTN + lane];
    const float w1 = cls_w[1 * DOUTN + lane];
    const float w2 = cls_w[2 * DOUTN + lane];
    const float w3 = cls_w[3 * DOUTN + lane];
    const float a0 = lw * w0, a1 = lw * w1, a2 = lw * w2, a3 = lw * w3;
    const float Sa0 = warp_sum(a0);
    const float Sa1 = warp_sum(a1);
    const float Sa2 = warp_sum(a2);
    const float Sa3 = warp_sum(a3);
    const float Sb0 = warp_sum(lb * w0) + cls_b[0];
    const float Sb1 = warp_sum(lb * w1) + cls_b[1];
    const float Sb2 = warp_sum(lb * w2) + cls_b[2];
    const float Sb3 = warp_sum(lb * w3) + cls_b[3];

    // ---- running state ----
    float m0 = 0.f, m1 = 0.f, m2_ = 0.f, m3 = 0.f;       // Welford mean
    float s0 = 0.f, s1 = 0.f, s2 = 0.f, s3 = 0.f;        // Welford M2
    float h = 0.f;                                       // EMA of r^2 (per lane j)
    float s_ema = 0.f;
    float tauf = 0.f;

    float* sZw = sZ[w];
    const float* zptr = z_ticks + (size_t)batch * TT * DD + lane * 4;
    float* ox = out_x + ((size_t)batch * TT) * DOUTN + lane;
    float* ol = out_logits + ((size_t)batch * TT) * CCLS + lane;

    // prefetch distance 2
    float4 zb0 = *(const float4*)(zptr);
    float4 zb1 = *(const float4*)(zptr + DD);

#pragma unroll 1
    for (int t = 0; t < TT; t++) {
        float4 z = zb0;
        zb0 = zb1;
        {
            int tp = t + 2; if (tp > TT - 1) tp = TT - 1;
            zb1 = *(const float4*)(zptr + (size_t)tp * DD);
        }

        tauf += 1.0f;
        const float inv_tau   = __fdividef(1.0f, tauf);
        const float denom     = fmaxf(tauf - 1.0f, 1.0f);
        const float inv_denom = __fdividef(1.0f, denom);
        s_ema = fmaf(GAMMA_C, s_ema, 1.0f);
        const float inv_s = __fdividef(1.0f, s_ema);

        // ---- Welford update (4 dims per thread) ----
        float d0 = z.x - m0, d1 = z.y - m1, d2 = z.z - m2_, d3 = z.w - m3;
        m0 = fmaf(d0, inv_tau, m0);
        m1 = fmaf(d1, inv_tau, m1);
        m2_ = fmaf(d2, inv_tau, m2_);
        m3 = fmaf(d3, inv_tau, m3);
        float e0 = z.x - m0, e1 = z.y - m1, e2 = z.z - m2_, e3 = z.w - m3;
        s0 = fmaf(d0, e0, s0);
        s1 = fmaf(d1, e1, s1);
        s2 = fmaf(d2, e2, s2);
        s3 = fmaf(d3, e3, s3);

        // v_bar = mean_d(M2)/denom  (one 5-stage butterfly)
        const float msum = (s0 + s1) + (s2 + s3);
        const float vbar = warp_sum(msum) * (inv_denom * (1.0f / 128.0f));

        // v_tilde + eps = M2 * c1 + c2 ;  z_tilde = e * rsqrt(.)
        const float c1 = (1.0f - ALPHA_C) * inv_denom;
        const float c2 = fmaf(ALPHA_C, vbar, EPS_C);
        const float zt0 = e0 * rsqrtf(fmaf(s0, c1, c2));
        const float zt1 = e1 * rsqrtf(fmaf(s1, c1, c2));
        const float zt2 = e2 * rsqrtf(fmaf(s2, c1, c2));
        const float zt3 = e3 * rsqrtf(fmaf(s3, c1, c2));

        ((float4*)sZw)[lane] = make_float4(zt0, zt1, zt2, zt3);
        __syncwarp();

        // ---- matvec: r[lane] = sum_d z_tilde[d] * proj[d][lane] (regs + f32x2) ----
        const ulonglong2* zp = (const ulonglong2*)sZw;
        unsigned long long acc0 = 0ull, acc1 = 0ull, acc2 = 0ull, acc3 = 0ull;
#pragma unroll
        for (int c = 0; c < 16; c++) {
            ulonglong2 za = zp[2 * c];
            ulonglong2 zc = zp[2 * c + 1];
            acc0 = fma2(za.x, q[4 * c + 0], acc0);
            acc1 = fma2(za.y, q[4 * c + 1], acc1);
            acc2 = fma2(zc.x, q[4 * c + 2], acc2);
            acc3 = fma2(zc.y, q[4 * c + 3], acc3);
        }
        __syncwarp();   // WAR: protect sZ before next iteration's store

        float f0, f1, f2, f3, f4, f5, f6, f7;
        unpack2(acc0, f0, f1);
        unpack2(acc1, f2, f3);
        unpack2(acc2, f4, f5);
        unpack2(acc3, f6, f7);
        const float r = ((f0 + f1) + (f2 + f3)) + ((f4 + f5) + (f6 + f7));

        // ---- h EMA, log feature ----
        h = fmaf(r, r, GAMMA_C * h);
        const float xv = __logf(fmaf(h, inv_s, EPSH_C));

        ox[(size_t)t * DOUTN] = xv;

        // ---- LayerNorm + classifier (folded): 6 independent butterflies,
        //      interleaved by stage so their SHFL latencies overlap ----
        float rx  = xv;
        float rx2 = xv * xv;
        float rd0 = xv * a0;
        float rd1 = xv * a1;
        float rd2 = xv * a2;
        float rd3 = xv * a3;
#pragma unroll
        for (int sft = 16; sft > 0; sft >>= 1) {
            rx  += __shfl_xor_sync(0xffffffffu, rx,  sft, 32);
            rx2 += __shfl_xor_sync(0xffffffffu, rx2, sft, 32);
            rd0 += __shfl_xor_sync(0xffffffffu, rd0, sft, 32);
            rd1 += __shfl_xor_sync(0xffffffffu, rd1, sft, 32);
            rd2 += __shfl_xor_sync(0xffffffffu, rd2, sft, 32);
            rd3 += __shfl_xor_sync(0xffffffffu, rd3, sft, 32);
        }

        const float mu      = rx * (1.0f / 32.0f);
        const float var     = fmaf(rx2, 1.0f / 32.0f, -mu * mu);
        const float inv_std = rsqrtf(var + LNEPS_C);

        if (lane < CCLS) {
            float dot = (lane == 0) ? rd0 : (lane == 1) ? rd1 : (lane == 2) ? rd2 : rd3;
            float Sa  = (lane == 0) ? Sa0 : (lane == 1) ? Sa1 : (lane == 2) ? Sa2 : Sa3;
            float Sb  = (lane == 0) ? Sb0 : (lane == 1) ? Sb1 : (lane == 2) ? Sb2 : Sb3;
            ol[(size_t)t * CCLS] = fmaf(inv_std, fmaf(-mu, Sa, dot), Sb);
        }
    }
}

extern "C" void kernel_launch(void* const* d_in, const int* in_sizes, int n_in,
                              void* d_out, int out_size) {
    const float* z_ticks = (const float*)d_in[0];
    const float* proj    = (const float*)d_in[1];
    const float* ln_w    = (const float*)d_in[2];
    const float* ln_b    = (const float*)d_in[3];
    const float* cls_w   = (const float*)d_in[4];
    const float* cls_b   = (const float*)d_in[5];

    float* out_x      = (float*)d_out;
    float* out_logits = out_x + (size_t)BATCH * TT * DOUTN;

    sync_head_kernel<<<BATCH / 4, 128>>>(z_ticks, proj, ln_w, ln_b,
                                         cls_w, cls_b, out_x, out_logits);
}

// round 4
// speedup vs baseline: 1.3515x; 1.3515x over previous
#include <cuda_runtime.h>
#include <cstddef>

#define BATCH 512
#define TT    512
#define DD    128
#define DOUTN 32
#define CCLS  4

#define ALPHA_C 0.1f
#define GAMMA_C 0.9f
#define EPS_C   1e-5f
#define EPSH_C  1e-6f
#define LNEPS_C 1e-5f

__device__ __forceinline__ float warp_sum(float v) {
#pragma unroll
    for (int s = 16; s > 0; s >>= 1)
        v += __shfl_xor_sync(0xffffffffu, v, s, 32);
    return v;
}

__device__ __forceinline__ unsigned long long fma2(unsigned long long a,
                                                   unsigned long long b,
                                                   unsigned long long c) {
    unsigned long long d;
    asm("fma.rn.f32x2 %0, %1, %2, %3;" : "=l"(d) : "l"(a), "l"(b), "l"(c));
    return d;
}

__device__ __forceinline__ unsigned long long pack2(float lo, float hi) {
    unsigned long long r;
    asm("mov.b64 %0, {%1, %2};" : "=l"(r) : "f"(lo), "f"(hi));
    return r;
}

__device__ __forceinline__ void unpack2(unsigned long long v, float& lo, float& hi) {
    asm("mov.b64 {%0, %1}, %2;" : "=f"(lo), "=f"(hi) : "l"(v));
}

// Packed 6-value warp reduction (sx, sx2, d0..d3) -> 14 shfl + selects.
// Results land: sx in lanes 0-3 (returned in u), sx2 in lanes 16-19,
// d0 in 4-7, d1 in 20-23, d2 in 8-11, d3 in 24-27.
__device__ __forceinline__ float packed_reduce6(float px, float px2,
                                                float pd0, float pd1,
                                                float pd2, float pd3,
                                                int lane) {
    px  += __shfl_xor_sync(0xffffffffu, px,  16, 32);
    px2 += __shfl_xor_sync(0xffffffffu, px2, 16, 32);
    pd0 += __shfl_xor_sync(0xffffffffu, pd0, 16, 32);
    pd1 += __shfl_xor_sync(0xffffffffu, pd1, 16, 32);
    pd2 += __shfl_xor_sync(0xffffffffu, pd2, 16, 32);
    pd3 += __shfl_xor_sync(0xffffffffu, pd3, 16, 32);
    const bool hi16 = (lane & 16) != 0;
    float pA = hi16 ? px2 : px;
    float pB = hi16 ? pd1 : pd0;
    float pC = hi16 ? pd3 : pd2;
    pA += __shfl_xor_sync(0xffffffffu, pA, 8, 32);
    pB += __shfl_xor_sync(0xffffffffu, pB, 8, 32);
    pC += __shfl_xor_sync(0xffffffffu, pC, 8, 32);
    pA += __shfl_xor_sync(0xffffffffu, pA, 4, 32);
    pB += __shfl_xor_sync(0xffffffffu, pB, 4, 32);
    pC += __shfl_xor_sync(0xffffffffu, pC, 4, 32);
    float u = (lane & 8) ? ((lane & 4) ? 0.0f : pC)
                         : ((lane & 4) ? pB : pA);
    u += __shfl_xor_sync(0xffffffffu, u, 2, 32);
    u += __shfl_xor_sync(0xffffffffu, u, 1, 32);
    return u;
}

__global__ __launch_bounds__(128, 1)
void sync_head_kernel(const float* __restrict__ z_ticks,
                      const float* __restrict__ proj,
                      const float* __restrict__ ln_w,
                      const float* __restrict__ ln_b,
                      const float* __restrict__ cls_w,
                      const float* __restrict__ cls_b,
                      float* __restrict__ out_x,
                      float* __restrict__ out_logits) {
    __shared__ __align__(16) float sZ[2][4][DD];
    __shared__ float4 cst[TT];   // (inv_tau, alpha*inv_denom/128, (1-alpha)*inv_denom, inv_s)

    const int lane  = threadIdx.x & 31;
    const int w     = threadIdx.x >> 5;
    const int batch = blockIdx.x * 4 + w;

    // ---- per-t constant table (parallel fill; pure functions of t) ----
    for (int t = threadIdx.x; t < TT; t += 128) {
        float tau = (float)(t + 1);
        float inv_tau = 1.0f / tau;
        float denom = fmaxf(tau - 1.0f, 1.0f);
        float inv_denom = 1.0f / denom;
        // s_ema(t) = (1 - gamma^{t+1}) / (1 - gamma)
        float g = __powf(GAMMA_C, tau);
        float s = (1.0f - g) / (1.0f - GAMMA_C);
        cst[t] = make_float4(inv_tau,
                             ALPHA_C * inv_denom * (1.0f / 128.0f),
                             (1.0f - ALPHA_C) * inv_denom,
                             1.0f / s);
    }

    // ---- hoist proj column `lane` into registers, packed for f32x2 FMA ----
    unsigned long long q[DD / 2];
#pragma unroll
    for (int i = 0; i < DD / 2; i++) {
        float a = proj[(2 * i) * DOUTN + lane];
        float b = proj[(2 * i + 1) * DOUTN + lane];
        q[i] = pack2(a, b);
    }

    // ---- fold LayerNorm affine + classifier into per-lane constants ----
    const float lw = ln_w[lane];
    const float lb = ln_b[lane];
    const float w0 = cls_w[0 * DOUTN + lane];
    const float w1 = cls_w[1 * DOUTN + lane];
    const float w2 = cls_w[2 * DOUTN + lane];
    const float w3 = cls_w[3 * DOUTN + lane];
    const float a0 = lw * w0, a1 = lw * w1, a2 = lw * w2, a3 = lw * w3;
    const float Sa0 = warp_sum(a0);
    const float Sa1 = warp_sum(a1);
    const float Sa2 = warp_sum(a2);
    const float Sa3 = warp_sum(a3);
    const float Sb0 = warp_sum(lb * w0) + cls_b[0];
    const float Sb1 = warp_sum(lb * w1) + cls_b[1];
    const float Sb2 = warp_sum(lb * w2) + cls_b[2];
    const float Sb3 = warp_sum(lb * w3) + cls_b[3];
    const float Sa_l = (lane == 0) ? Sa0 : (lane == 1) ? Sa1 : (lane == 2) ? Sa2 : Sa3;
    const float Sb_l = (lane == 0) ? Sb0 : (lane == 1) ? Sb1 : (lane == 2) ? Sb2 : Sb3;
    // source lane for this lane's classifier dot after packed_reduce6
    const int dsrc = ((lane & 1) << 4) | ((lane & 2) ? 8 : 4);

    __syncthreads();   // cst table ready

    // ---- running state ----
    float m0 = 0.f, m1 = 0.f, m2_ = 0.f, m3 = 0.f;
    float s0 = 0.f, s1 = 0.f, s2 = 0.f, s3 = 0.f;
    float h = 0.f;
    // pending epilogue values (step t-1), reduced during step t
    float px = 0.f, px2 = 0.f, pd0 = 0.f, pd1 = 0.f, pd2 = 0.f, pd3 = 0.f;

    const float* zptr = z_ticks + (size_t)batch * TT * DD + lane * 4;
    float* ox  = out_x + ((size_t)batch * TT) * DOUTN + lane;
    float* olb = out_logits + ((size_t)batch * TT) * CCLS + lane;

    float4 zb0 = *(const float4*)(zptr);
    float4 zb1 = *(const float4*)(zptr + DD);

#pragma unroll 1
    for (int t = 0; t < TT; t++) {
        const float4 z = zb0;
        zb0 = zb1;
        {
            int tp = t + 2; if (tp > TT - 1) tp = TT - 1;
            zb1 = *(const float4*)(zptr + (size_t)tp * DD);
        }
        const float4 C = cst[t];   // LDS.128 broadcast

        // ---- Welford update (4 dims per thread) ----
        float d0 = z.x - m0, d1 = z.y - m1, d2 = z.z - m2_, d3 = z.w - m3;
        m0 = fmaf(d0, C.x, m0);
        m1 = fmaf(d1, C.x, m1);
        m2_ = fmaf(d2, C.x, m2_);
        m3 = fmaf(d3, C.x, m3);
        float e0 = z.x - m0, e1 = z.y - m1, e2 = z.z - m2_, e3 = z.w - m3;
        s0 = fmaf(d0, e0, s0);
        s1 = fmaf(d1, e1, s1);
        s2 = fmaf(d2, e2, s2);
        s3 = fmaf(d3, e3, s3);
        const float msum = (s0 + s1) + (s2 + s3);

        // ---- merged reductions: msum butterfly (5) interleaved with
        //      pending-epilogue packed reduction (14) ----
        float b = msum;
        b   += __shfl_xor_sync(0xffffffffu, b,   16, 32);
        px  += __shfl_xor_sync(0xffffffffu, px,  16, 32);
        px2 += __shfl_xor_sync(0xffffffffu, px2, 16, 32);
        pd0 += __shfl_xor_sync(0xffffffffu, pd0, 16, 32);
        pd1 += __shfl_xor_sync(0xffffffffu, pd1, 16, 32);
        pd2 += __shfl_xor_sync(0xffffffffu, pd2, 16, 32);
        pd3 += __shfl_xor_sync(0xffffffffu, pd3, 16, 32);
        b += __shfl_xor_sync(0xffffffffu, b, 8, 32);
        const bool hi16 = (lane & 16) != 0;
        float pA = hi16 ? px2 : px;
        float pB = hi16 ? pd1 : pd0;
        float pC = hi16 ? pd3 : pd2;
        pA += __shfl_xor_sync(0xffffffffu, pA, 8, 32);
        pB += __shfl_xor_sync(0xffffffffu, pB, 8, 32);
        pC += __shfl_xor_sync(0xffffffffu, pC, 8, 32);
        b  += __shfl_xor_sync(0xffffffffu, b, 4, 32);
        pA += __shfl_xor_sync(0xffffffffu, pA, 4, 32);
        pB += __shfl_xor_sync(0xffffffffu, pB, 4, 32);
        pC += __shfl_xor_sync(0xffffffffu, pC, 4, 32);
        b  += __shfl_xor_sync(0xffffffffu, b, 2, 32);
        float u = (lane & 8) ? ((lane & 4) ? 0.0f : pC)
                             : ((lane & 4) ? pB : pA);
        u += __shfl_xor_sync(0xffffffffu, u, 2, 32);
        b += __shfl_xor_sync(0xffffffffu, b, 1, 32);
        u += __shfl_xor_sync(0xffffffffu, u, 1, 32);
        const float sx2v = __shfl_sync(0xffffffffu, u, 16, 32);
        const float dotv = __shfl_sync(0xffffffffu, u, dsrc, 32);

        // c2 = alpha*vbar + eps, folded: b * (alpha*inv_denom/128) + eps
        const float c2 = fmaf(b, C.y, EPS_C);
        const float zt0 = e0 * rsqrtf(fmaf(s0, C.z, c2));
        const float zt1 = e1 * rsqrtf(fmaf(s1, C.z, c2));
        const float zt2 = e2 * rsqrtf(fmaf(s2, C.z, c2));
        const float zt3 = e3 * rsqrtf(fmaf(s3, C.z, c2));

        // ---- store logits for step t-1 (overlaps with front-end above) ----
        if (t > 0 && lane < CCLS) {
            const float mu      = u * (1.0f / 32.0f);
            const float var     = fmaf(sx2v, 1.0f / 32.0f, -mu * mu);
            const float inv_std = rsqrtf(var + LNEPS_C);
            olb[(size_t)(t - 1) * CCLS] = fmaf(inv_std, fmaf(-mu, Sa_l, dotv), Sb_l);
        }

        float* sb = sZ[t & 1][w];
        ((float4*)sb)[lane] = make_float4(zt0, zt1, zt2, zt3);
        __syncwarp();

        // ---- matvec: r[lane] = sum_d z_tilde[d] * proj[d][lane] ----
        const ulonglong2* zp = (const ulonglong2*)sb;
        unsigned long long acc0 = 0ull, acc1 = 0ull, acc2 = 0ull, acc3 = 0ull;
#pragma unroll
        for (int c = 0; c < 16; c++) {
            ulonglong2 za = zp[2 * c];
            ulonglong2 zc = zp[2 * c + 1];
            acc0 = fma2(za.x, q[4 * c + 0], acc0);
            acc1 = fma2(za.y, q[4 * c + 1], acc1);
            acc2 = fma2(zc.x, q[4 * c + 2], acc2);
            acc3 = fma2(zc.y, q[4 * c + 3], acc3);
        }

        float f0, f1, f2, f3, f4, f5, f6, f7;
        unpack2(acc0, f0, f1);
        unpack2(acc1, f2, f3);
        unpack2(acc2, f4, f5);
        unpack2(acc3, f6, f7);
        const float r = ((f0 + f1) + (f2 + f3)) + ((f4 + f5) + (f6 + f7));

        // ---- h EMA, log feature ----
        h = fmaf(r, r, GAMMA_C * h);
        const float xv = __logf(fmaf(h, C.w, EPSH_C));
        ox[(size_t)t * DOUTN] = xv;

        // ---- queue epilogue values for next iteration's merged reduction ----
        px  = xv;
        px2 = xv * xv;
        pd0 = xv * a0;
        pd1 = xv * a1;
        pd2 = xv * a2;
        pd3 = xv * a3;
    }

    // ---- final epilogue for t = TT-1 ----
    {
        const float u = packed_reduce6(px, px2, pd0, pd1, pd2, pd3, lane);
        const float sx2v = __shfl_sync(0xffffffffu, u, 16, 32);
        const float dotv = __shfl_sync(0xffffffffu, u, dsrc, 32);
        if (lane < CCLS) {
            const float mu      = u * (1.0f / 32.0f);
            const float var     = fmaf(sx2v, 1.0f / 32.0f, -mu * mu);
            const float inv_std = rsqrtf(var + LNEPS_C);
            olb[(size_t)(TT - 1) * CCLS] = fmaf(inv_std, fmaf(-mu, Sa_l, dotv), Sb_l);
        }
    }
}

extern "C" void kernel_launch(void* const* d_in, const int* in_sizes, int n_in,
                              void* d_out, int out_size) {
    const float* z_ticks = (const float*)d_in[0];
    const float* proj    = (const float*)d_in[1];
    const float* ln_w    = (const float*)d_in[2];
    const float* ln_b    = (const float*)d_in[3];
    const float* cls_w   = (const float*)d_in[4];
    const float* cls_b   = (const float*)d_in[5];

    float* out_x      = (float*)d_out;
    float* out_logits = out_x + (size_t)BATCH * TT * DOUTN;

    sync_head_kernel<<<BATCH / 4, 128>>>(z_ticks, proj, ln_w, ln_b,
                                         cls_w, cls_b, out_x, out_logits);
}